// round 1
// baseline (speedup 1.0000x reference)
#include <cuda_runtime.h>
#include <math.h>

#define NB 8192
#define NT 256

// smem h1 padded stride: 33 floats per (row,col) cell to avoid bank conflicts
#define H1_PAD 33

__global__ __launch_bounds__(NT, 2) void moe_fused_kernel(
    const float* __restrict__ x,    // [B,28,28,1]
    const float* __restrict__ w1,   // [3,3,1,32]
    const float* __restrict__ b1,   // [32]
    const float* __restrict__ w2,   // [3,3,32,64]
    const float* __restrict__ b2,   // [64]
    const float* __restrict__ gw,   // [1600,5]
    const float* __restrict__ gb,   // [5]
    const float* __restrict__ ew,   // [5,1600,10]
    const float* __restrict__ eb,   // [5,10]
    float* __restrict__ out)        // [B,10]
{
    __shared__ float s_x[784];
    __shared__ float s_w1[288];
    __shared__ float s_b1[32];
    __shared__ float s_b2[64];
    __shared__ float s_h1[169 * H1_PAD];   // [13*13][33]
    __shared__ float s_feat[1600];
    __shared__ float s_dot[64];            // 55 used: 5 gate logits + 50 expert outs

    const int b = blockIdx.x;
    const int t = threadIdx.x;

    // ---------------- Phase 1: stage inputs ----------------
    {
        const float* xi = x + b * 784;
        for (int i = t; i < 784; i += NT) s_x[i] = xi[i];
        for (int i = t; i < 288; i += NT) s_w1[i] = w1[i];
        if (t < 32) s_b1[t] = b1[t];
        if (t < 64) s_b2[t] = b2[t];
    }
    __syncthreads();

    // ---------------- Phase 2: conv1 + relu + maxpool2 -> h1 [13,13,32] ----------------
    // 5408 outputs; i -> (spatial sp = i>>5, channel c = i&31). Warp shares sp (broadcast x).
    for (int i = t; i < 5408; i += NT) {
        const int c  = i & 31;
        const int sp = i >> 5;            // 0..168
        const int px = sp % 13, py = sp / 13;
        const float bias = s_b1[c];
        float m = 0.0f;                   // relu floor
        #pragma unroll
        for (int dy = 0; dy < 2; dy++) {
            #pragma unroll
            for (int dx = 0; dx < 2; dx++) {
                const int oy = 2 * py + dy, ox = 2 * px + dx;
                float acc = bias;
                #pragma unroll
                for (int ky = 0; ky < 3; ky++)
                    #pragma unroll
                    for (int kx = 0; kx < 3; kx++)
                        acc = fmaf(s_x[(oy + ky) * 28 + ox + kx],
                                   s_w1[(ky * 3 + kx) * 32 + c], acc);
                m = fmaxf(m, acc);
            }
        }
        s_h1[sp * H1_PAD + c] = m;        // relu(max) == max(relu) since max>=0 kept via floor
    }
    __syncthreads();

    // ---------------- Phase 3: conv2 + relu + maxpool2 -> feat [5,5,64] ----------------
    // 200 work units: (pool cell s in 0..24) x (co-group cg in 0..7, 8 channels each).
    // Each thread: acc[4 pool positions][8 co] register block.
    if (t < 200) {
        const int s  = t >> 3;            // 0..24
        const int cg = t & 7;             // 0..7
        const int qy = s / 5, qx = s % 5;
        const int co0 = cg * 8;

        float acc[4][8];
        #pragma unroll
        for (int p = 0; p < 4; p++)
            #pragma unroll
            for (int j = 0; j < 8; j++) acc[p][j] = 0.0f;

        #pragma unroll
        for (int ky = 0; ky < 3; ky++) {
            #pragma unroll
            for (int kx = 0; kx < 3; kx++) {
                const int r0 = 2 * qy + ky;
                const int c0 = 2 * qx + kx;
                const float* h00 = s_h1 + (r0 * 13 + c0) * H1_PAD;
                const float* h01 = h00 + H1_PAD;
                const float* h10 = h00 + 13 * H1_PAD;
                const float* h11 = h10 + H1_PAD;
                const float* wp  = w2 + ((ky * 3 + kx) * 32) * 64 + co0;

                #pragma unroll 4
                for (int ci = 0; ci < 32; ci++) {
                    const float4 wa = *(const float4*)(wp + ci * 64);
                    const float4 wb = *(const float4*)(wp + ci * 64 + 4);
                    const float w[8] = {wa.x, wa.y, wa.z, wa.w, wb.x, wb.y, wb.z, wb.w};
                    const float hv[4] = {h00[ci], h01[ci], h10[ci], h11[ci]};
                    #pragma unroll
                    for (int p = 0; p < 4; p++)
                        #pragma unroll
                        for (int j = 0; j < 8; j++)
                            acc[p][j] = fmaf(hv[p], w[j], acc[p][j]);
                }
            }
        }
        const int fbase = (qy * 5 + qx) * 64 + co0;
        #pragma unroll
        for (int j = 0; j < 8; j++) {
            const float bb = s_b2[co0 + j];
            float m = acc[0][j];
            m = fmaxf(m, acc[1][j]);
            m = fmaxf(m, acc[2][j]);
            m = fmaxf(m, acc[3][j]);
            s_feat[fbase + j] = fmaxf(m + bb, 0.0f);   // relu(maxpool)
        }
    }
    __syncthreads();

    // ---------------- Phase 4: 55 dot products (5 gate + 5x10 experts) ----------------
    {
        const int wid  = t >> 5;
        const int lane = t & 31;
        for (int j = wid; j < 55; j += 8) {
            const float* wv;
            int stride;
            float bias;
            if (j < 5) { wv = gw + j; stride = 5; bias = gb[j]; }
            else {
                const int e = (j - 5) / 10, c = (j - 5) % 10;
                wv = ew + (e * 1600) * 10 + c; stride = 10; bias = eb[j - 5];
            }
            float sum = 0.0f;
            for (int d = lane; d < 1600; d += 32)
                sum = fmaf(s_feat[d], wv[d * stride], sum);
            #pragma unroll
            for (int o = 16; o; o >>= 1)
                sum += __shfl_xor_sync(0xFFFFFFFFu, sum, o);
            if (lane == 0) s_dot[j] = sum + bias;
        }
    }
    __syncthreads();

    // ---------------- Phase 5: gate softmax, top-3, combine, final softmax ----------------
    if (t == 0) {
        float p[5];
        float gm = -1e30f;
        #pragma unroll
        for (int e = 0; e < 5; e++) gm = fmaxf(gm, s_dot[e]);
        float gsum = 0.0f;
        #pragma unroll
        for (int e = 0; e < 5; e++) { p[e] = expf(s_dot[e] - gm); gsum += p[e]; }
        const float ginv = 1.0f / gsum;
        #pragma unroll
        for (int e = 0; e < 5; e++) p[e] *= ginv;

        // stable top-3 (ties -> lower index), matching lax.top_k
        int idx[5] = {0, 1, 2, 3, 4};
        #pragma unroll
        for (int a = 0; a < 3; a++) {
            int best = a;
            #pragma unroll
            for (int q = a + 1; q < 5; q++)
                if (p[idx[q]] > p[idx[best]]) best = q;
            const int tmp = idx[a]; idx[a] = idx[best]; idx[best] = tmp;
        }

        float comb[10];
        #pragma unroll
        for (int c = 0; c < 10; c++) {
            float v = 0.0f;
            #pragma unroll
            for (int k = 0; k < 3; k++)
                v = fmaf(p[idx[k]], s_dot[5 + idx[k] * 10 + c], v);
            comb[c] = v;
        }
        float cm = -1e30f;
        #pragma unroll
        for (int c = 0; c < 10; c++) cm = fmaxf(cm, comb[c]);
        float cs = 0.0f;
        float ex[10];
        #pragma unroll
        for (int c = 0; c < 10; c++) { ex[c] = expf(comb[c] - cm); cs += ex[c]; }
        const float inv = 1.0f / cs;
        float* o = out + b * 10;
        #pragma unroll
        for (int c = 0; c < 10; c++) o[c] = ex[c] * inv;
    }
}

extern "C" void kernel_launch(void* const* d_in, const int* in_sizes, int n_in,
                              void* d_out, int out_size) {
    const float* x  = (const float*)d_in[0];
    const float* w1 = (const float*)d_in[1];
    const float* b1 = (const float*)d_in[2];
    const float* w2 = (const float*)d_in[3];
    const float* b2 = (const float*)d_in[4];
    const float* gw = (const float*)d_in[5];
    const float* gb = (const float*)d_in[6];
    const float* ew = (const float*)d_in[7];
    const float* eb = (const float*)d_in[8];
    float* out = (float*)d_out;

    moe_fused_kernel<<<NB, NT>>>(x, w1, b1, w2, b2, gw, gb, ew, eb, out);
}

// round 2
// speedup vs baseline: 1.1676x; 1.1676x over previous
#include <cuda_runtime.h>
#include <math.h>

#define B        8192
#define IMG_PB   2
#define NBLK     (B / IMG_PB)     // 4096
#define NT       256

// ---------------- global scratch (no allocs allowed) ----------------
__device__ float g_feat[B * 1600];        // [B][25][64] flattened (y,x,co)
__device__ float g_wpack[1600 * 56];      // [d][j]: j<5 gate, 5..54 experts, 55 pad

// ==================== K0: pack gate+expert weights ====================
__global__ void pack_weights_kernel(const float* __restrict__ gw,
                                    const float* __restrict__ ew) {
    int i = blockIdx.x * blockDim.x + threadIdx.x;
    if (i >= 1600 * 56) return;
    int d = i / 56, j = i - d * 56;
    float v = 0.0f;
    if (j < 5)       v = gw[d * 5 + j];
    else if (j < 55) {
        int e = (j - 5) / 10, c = (j - 5) % 10;
        v = ew[(e * 1600 + d) * 10 + c];
    }
    g_wpack[i] = v;
}

// ==================== K1: conv1+pool + conv2+pool (2 images / block) ====================
// dyn smem layout (floats):
//   s_h  [2*169*32] = 10816   pooled conv1 output, [img][sp][ci]
//   s_w2 [3*32*64]  =  6144   w2 chunk for current ky, [kx][ci][co]
//   s_x  [2*784]    =  1568
//   s_w1 [288], s_b1[32], s_b2[64]
#define SME_FLOATS (10816 + 6144 + 1568 + 288 + 32 + 64)

__global__ __launch_bounds__(NT, 2) void conv_fused_kernel(
    const float* __restrict__ x,    // [B,28,28,1]
    const float* __restrict__ w1,   // [3,3,1,32]
    const float* __restrict__ b1,   // [32]
    const float* __restrict__ w2,   // [3,3,32,64]
    const float* __restrict__ b2)   // [64]
{
    extern __shared__ float sm[];
    float* s_h  = sm;
    float* s_w2 = s_h + 10816;
    float* s_x  = s_w2 + 6144;
    float* s_w1 = s_x + 1568;
    float* s_b1 = s_w1 + 288;
    float* s_b2 = s_b1 + 32;

    const int t  = threadIdx.x;
    const int b0 = blockIdx.x * IMG_PB;

    // ---- stage x (2 images), w1, biases ----
    {
        const float* xi = x + b0 * 784;
        for (int i = t; i < 1568; i += NT) s_x[i] = xi[i];
        for (int i = t; i < 288; i += NT) s_w1[i] = w1[i];
        if (t < 32) s_b1[t] = b1[t];
        if (t < 64) s_b2[t] = b2[t];
    }
    __syncthreads();

    // ---- phase A: conv1 + relu + pool -> s_h ----
    // 1352 units: (img, cell 0..168, ch-group of 8)
    for (int i = t; i < 1352; i += NT) {
        const int img  = i / 676;
        const int r    = i - img * 676;
        const int cell = r >> 2;
        const int c0   = (r & 3) * 8;
        const int qy = cell / 13, qx = cell - qy * 13;
        const float* xb = s_x + img * 784 + (2 * qy) * 28 + 2 * qx;

        float acc[4][8];
        #pragma unroll
        for (int p = 0; p < 4; p++)
            #pragma unroll
            for (int j = 0; j < 8; j++) acc[p][j] = 0.0f;

        #pragma unroll
        for (int ky = 0; ky < 3; ky++) {
            #pragma unroll
            for (int kx = 0; kx < 3; kx++) {
                const float* xp = xb + ky * 28 + kx;
                const float xs[4] = { xp[0], xp[1], xp[28], xp[29] };
                const float* wq = s_w1 + (ky * 3 + kx) * 32 + c0;
                const float4 wA = *(const float4*)wq;
                const float4 wB = *(const float4*)(wq + 4);
                #pragma unroll
                for (int p = 0; p < 4; p++) {
                    const float hx = xs[p];
                    acc[p][0] = fmaf(hx, wA.x, acc[p][0]);
                    acc[p][1] = fmaf(hx, wA.y, acc[p][1]);
                    acc[p][2] = fmaf(hx, wA.z, acc[p][2]);
                    acc[p][3] = fmaf(hx, wA.w, acc[p][3]);
                    acc[p][4] = fmaf(hx, wB.x, acc[p][4]);
                    acc[p][5] = fmaf(hx, wB.y, acc[p][5]);
                    acc[p][6] = fmaf(hx, wB.z, acc[p][6]);
                    acc[p][7] = fmaf(hx, wB.w, acc[p][7]);
                }
            }
        }
        float* hb = s_h + (img * 169 + cell) * 32 + c0;
        #pragma unroll
        for (int j = 0; j < 8; j++) {
            float m = fmaxf(fmaxf(acc[0][j], acc[1][j]), fmaxf(acc[2][j], acc[3][j]));
            hb[j] = fmaxf(m + s_b1[c0 + j], 0.0f);
        }
    }

    // ---- phase B: conv2 + relu + pool -> g_feat ----
    // 200 compute threads: (cell 0..49) x (co-group of 16)
    const bool active = t < 200;
    const int cell = t >> 2;
    const int co0  = (t & 3) * 16;
    const int img  = cell / 25;
    const int c25  = cell - img * 25;
    const int qy = c25 / 5, qx = c25 - qy * 5;
    const float* hb = s_h + img * (169 * 32);

    float acc[4][16];
    #pragma unroll
    for (int p = 0; p < 4; p++)
        #pragma unroll
        for (int j = 0; j < 16; j++) acc[p][j] = 0.0f;

    for (int ky = 0; ky < 3; ky++) {
        __syncthreads();
        // stage w2 chunk for this ky: [3][32][64] = 6144 floats, coalesced
        {
            const float4* src = (const float4*)(w2 + ky * 6144);
            float4* dst = (float4*)s_w2;
            for (int i = t; i < 1536; i += NT) dst[i] = src[i];
        }
        __syncthreads();

        if (active) {
            #pragma unroll
            for (int kx = 0; kx < 3; kx++) {
                const int r0 = 2 * qy + ky;
                const int cc = 2 * qx + kx;
                const float* hp = hb + (r0 * 13 + cc) * 32;
                const float* wbase = s_w2 + (kx * 32) * 64 + co0;

                #pragma unroll 2
                for (int ci = 0; ci < 32; ci += 2) {
                    const float2 h0 = *(const float2*)(hp + ci);
                    const float2 h1 = *(const float2*)(hp + 32 + ci);
                    const float2 h2 = *(const float2*)(hp + 416 + ci);
                    const float2 h3 = *(const float2*)(hp + 448 + ci);
                    const float* wp = wbase + ci * 64;

                    float4 w4[4];
                    #pragma unroll
                    for (int jj = 0; jj < 4; jj++) w4[jj] = *(const float4*)(wp + 4 * jj);
                    {
                        const float hv[4] = { h0.x, h1.x, h2.x, h3.x };
                        #pragma unroll
                        for (int p = 0; p < 4; p++) {
                            const float hx = hv[p];
                            #pragma unroll
                            for (int jj = 0; jj < 4; jj++) {
                                acc[p][4*jj+0] = fmaf(hx, w4[jj].x, acc[p][4*jj+0]);
                                acc[p][4*jj+1] = fmaf(hx, w4[jj].y, acc[p][4*jj+1]);
                                acc[p][4*jj+2] = fmaf(hx, w4[jj].z, acc[p][4*jj+2]);
                                acc[p][4*jj+3] = fmaf(hx, w4[jj].w, acc[p][4*jj+3]);
                            }
                        }
                    }
                    #pragma unroll
                    for (int jj = 0; jj < 4; jj++) w4[jj] = *(const float4*)(wp + 64 + 4 * jj);
                    {
                        const float hv[4] = { h0.y, h1.y, h2.y, h3.y };
                        #pragma unroll
                        for (int p = 0; p < 4; p++) {
                            const float hx = hv[p];
                            #pragma unroll
                            for (int jj = 0; jj < 4; jj++) {
                                acc[p][4*jj+0] = fmaf(hx, w4[jj].x, acc[p][4*jj+0]);
                                acc[p][4*jj+1] = fmaf(hx, w4[jj].y, acc[p][4*jj+1]);
                                acc[p][4*jj+2] = fmaf(hx, w4[jj].z, acc[p][4*jj+2]);
                                acc[p][4*jj+3] = fmaf(hx, w4[jj].w, acc[p][4*jj+3]);
                            }
                        }
                    }
                }
            }
        }
    }

    if (active) {
        const int b = b0 + img;
        float* fo = g_feat + (b * 25 + c25) * 64 + co0;
        #pragma unroll
        for (int j = 0; j < 16; j++) {
            float m = fmaxf(fmaxf(acc[0][j], acc[1][j]), fmaxf(acc[2][j], acc[3][j]));
            fo[j] = fmaxf(m + s_b2[co0 + j], 0.0f);
        }
    }
}

// ==================== K2: batched gate/expert GEMM + MoE epilogue ====================
// grid 64 blocks x 128 rows; [8192,1600] x [1600,56packed]
#define KC 64
__global__ __launch_bounds__(256) void moe_head_kernel(
    const float* __restrict__ gb,   // [5]
    const float* __restrict__ eb,   // [5,10]
    float* __restrict__ out)        // [B,10]
{
    __shared__ float s_f[128 * 65];          // feat chunk, stride 65 (bank = row%32)
    __shared__ float s_w[KC * 56];
    __shared__ float s_bias[56];

    const int t = threadIdx.x;
    const int row0 = blockIdx.x * 128;
    const int rg = t & 31;          // rows rg, rg+32, rg+64, rg+96
    const int cg = t >> 5;          // cols cg*7 .. cg*7+6
    const int cbase = cg * 7;

    if (t < 56) s_bias[t] = (t < 5) ? gb[t] : ((t < 55) ? eb[t - 5] : 0.0f);

    float acc[4][7];
    #pragma unroll
    for (int i = 0; i < 4; i++)
        #pragma unroll
        for (int j = 0; j < 7; j++) acc[i][j] = 0.0f;

    for (int k0 = 0; k0 < 1600; k0 += KC) {
        __syncthreads();
        // stage feat: 128 rows x KC cols (coalesced LDG, odd-stride STS)
        for (int i = t; i < 128 * KC; i += 256) {
            const int r = i >> 6, c = i & 63;
            s_f[r * 65 + c] = g_feat[(row0 + r) * 1600 + k0 + c];
        }
        // stage packed weights: KC x 56 contiguous
        for (int i = t; i < KC * 56; i += 256)
            s_w[i] = g_wpack[k0 * 56 + i];
        __syncthreads();

        #pragma unroll 4
        for (int kk = 0; kk < KC; kk++) {
            const float f0 = s_f[(rg      ) * 65 + kk];
            const float f1 = s_f[(rg + 32 ) * 65 + kk];
            const float f2 = s_f[(rg + 64 ) * 65 + kk];
            const float f3 = s_f[(rg + 96 ) * 65 + kk];
            const float* wr = s_w + kk * 56 + cbase;
            #pragma unroll
            for (int j = 0; j < 7; j++) {
                const float wv = wr[j];
                acc[0][j] = fmaf(f0, wv, acc[0][j]);
                acc[1][j] = fmaf(f1, wv, acc[1][j]);
                acc[2][j] = fmaf(f2, wv, acc[2][j]);
                acc[3][j] = fmaf(f3, wv, acc[3][j]);
            }
        }
    }

    // write logits (+bias) to smem, reusing s_f region with stride 57
    __syncthreads();
    float* s_l = s_f;
    #pragma unroll
    for (int i = 0; i < 4; i++) {
        const int r = rg + 32 * i;
        #pragma unroll
        for (int j = 0; j < 7; j++)
            s_l[r * 57 + cbase + j] = acc[i][j] + s_bias[cbase + j];
    }
    __syncthreads();

    // per-row MoE epilogue: gate softmax, top-3, combine, final softmax
    if (t < 128) {
        const float* L = s_l + t * 57;
        float p[5];
        float gm = -1e30f;
        #pragma unroll
        for (int e = 0; e < 5; e++) gm = fmaxf(gm, L[e]);
        float gsum = 0.0f;
        #pragma unroll
        for (int e = 0; e < 5; e++) { p[e] = expf(L[e] - gm); gsum += p[e]; }
        const float ginv = 1.0f / gsum;
        #pragma unroll
        for (int e = 0; e < 5; e++) p[e] *= ginv;

        int idx[5] = {0, 1, 2, 3, 4};
        #pragma unroll
        for (int a = 0; a < 3; a++) {
            int best = a;
            #pragma unroll
            for (int q = a + 1; q < 5; q++)
                if (p[idx[q]] > p[idx[best]]) best = q;
            const int tmp = idx[a]; idx[a] = idx[best]; idx[best] = tmp;
        }

        float comb[10];
        #pragma unroll
        for (int c = 0; c < 10; c++) {
            float v = 0.0f;
            #pragma unroll
            for (int k = 0; k < 3; k++)
                v = fmaf(p[idx[k]], L[5 + idx[k] * 10 + c], v);
            comb[c] = v;
        }
        float cm = -1e30f;
        #pragma unroll
        for (int c = 0; c < 10; c++) cm = fmaxf(cm, comb[c]);
        float cs = 0.0f;
        float ex[10];
        #pragma unroll
        for (int c = 0; c < 10; c++) { ex[c] = expf(comb[c] - cm); cs += ex[c]; }
        const float inv = 1.0f / cs;
        float* o = out + (row0 + t) * 10;
        #pragma unroll
        for (int c = 0; c < 10; c++) o[c] = ex[c] * inv;
    }
}

// ==================== launcher ====================
extern "C" void kernel_launch(void* const* d_in, const int* in_sizes, int n_in,
                              void* d_out, int out_size) {
    const float* x  = (const float*)d_in[0];
    const float* w1 = (const float*)d_in[1];
    const float* b1 = (const float*)d_in[2];
    const float* w2 = (const float*)d_in[3];
    const float* b2 = (const float*)d_in[4];
    const float* gw = (const float*)d_in[5];
    const float* gb = (const float*)d_in[6];
    const float* ew = (const float*)d_in[7];
    const float* eb = (const float*)d_in[8];
    float* out = (float*)d_out;

    static const size_t smem_bytes = SME_FLOATS * sizeof(float);
    cudaFuncSetAttribute(conv_fused_kernel,
                         cudaFuncAttributeMaxDynamicSharedMemorySize, (int)smem_bytes);

    pack_weights_kernel<<<(1600 * 56 + 255) / 256, 256>>>(gw, ew);
    conv_fused_kernel<<<NBLK, NT, smem_bytes>>>(x, w1, b1, w2, b2);
    moe_head_kernel<<<B / 128, 256>>>(gb, eb, out);
}

// round 6
// speedup vs baseline: 1.5059x; 1.2898x over previous
#include <cuda_runtime.h>
#include <math.h>

#define B        8192
#define IMG_PB   2
#define NBLK     (B / IMG_PB)     // 4096
#define NT       256

// h1 pooled output stride per (row,col) cell: 34 floats (32 ch + 2 pad) -> bank spread
#define HS 34

// ---------------- global scratch (no allocs allowed) ----------------
__device__ float g_feat[B * 1600];        // [B][25cells][64co]

// ==================== K1: conv1+pool + conv2+pool (2 images / block) ====================
// dyn smem (floats): s_h 2*169*34=11492 | s_w2 slice 6144 | s_x 1568 | s_w1 288 | s_b1 32 | s_b2 64
#define SME_FLOATS (11492 + 6144 + 1568 + 288 + 32 + 64)

__global__ __launch_bounds__(NT, 2) void conv_fused_kernel(
    const float* __restrict__ x,    // [B,28,28,1]
    const float* __restrict__ w1,   // [3,3,1,32]
    const float* __restrict__ b1,   // [32]
    const float* __restrict__ w2,   // [3,3,32,64] = 18432 floats
    const float* __restrict__ b2)   // [64]
{
    extern __shared__ float sm[];
    float* s_h  = sm;                       // [2*169][34]
    float* s_w2 = s_h + 11492;              // one ky slice: [3 kx][32 ci][64 co] = 6144
    float* s_x  = s_w2 + 6144;              // [2][784]
    float* s_w1 = s_x + 1568;               // [9 taps][32]
    float* s_b1 = s_w1 + 288;
    float* s_b2 = s_b1 + 32;

    const int t  = threadIdx.x;
    const int b0 = blockIdx.x * IMG_PB;

    // ---- stage x, w1, biases ----
    {
        const float* xi = x + b0 * 784;
        for (int i = t; i < 1568; i += NT) s_x[i] = xi[i];
        for (int i = t; i < 288; i += NT) s_w1[i] = w1[i];
        if (t < 32) s_b1[t] = b1[t];
        if (t < 64) s_b2[t] = b2[t];
    }
    __syncthreads();

    // ---- phase A: conv1 + relu + pool -> s_h (stride HS) ----
    for (int i = t; i < 1352; i += NT) {
        const int img  = i / 676;
        const int r    = i - img * 676;
        const int cell = r >> 2;
        const int c0   = (r & 3) * 8;
        const int qy = cell / 13, qx = cell - qy * 13;
        const float* xb = s_x + img * 784 + (2 * qy) * 28 + 2 * qx;

        float acc[4][8];
        #pragma unroll
        for (int p = 0; p < 4; p++)
            #pragma unroll
            for (int j = 0; j < 8; j++) acc[p][j] = 0.0f;

        #pragma unroll
        for (int ky = 0; ky < 3; ky++) {
            #pragma unroll
            for (int kx = 0; kx < 3; kx++) {
                const float* xp = xb + ky * 28 + kx;
                const float xs[4] = { xp[0], xp[1], xp[28], xp[29] };
                const float* wq = s_w1 + (ky * 3 + kx) * 32 + c0;
                const float4 wA = *(const float4*)wq;
                const float4 wB = *(const float4*)(wq + 4);
                #pragma unroll
                for (int p = 0; p < 4; p++) {
                    const float hx = xs[p];
                    acc[p][0] = fmaf(hx, wA.x, acc[p][0]);
                    acc[p][1] = fmaf(hx, wA.y, acc[p][1]);
                    acc[p][2] = fmaf(hx, wA.z, acc[p][2]);
                    acc[p][3] = fmaf(hx, wA.w, acc[p][3]);
                    acc[p][4] = fmaf(hx, wB.x, acc[p][4]);
                    acc[p][5] = fmaf(hx, wB.y, acc[p][5]);
                    acc[p][6] = fmaf(hx, wB.z, acc[p][6]);
                    acc[p][7] = fmaf(hx, wB.w, acc[p][7]);
                }
            }
        }
        float* hb = s_h + (img * 169 + cell) * HS + c0;
        #pragma unroll
        for (int j = 0; j < 8; j += 2) {
            float2 v;
            v.x = fmaxf(fmaxf(fmaxf(acc[0][j],   acc[1][j]),   fmaxf(acc[2][j],   acc[3][j]))   + s_b1[c0+j],   0.0f);
            v.y = fmaxf(fmaxf(fmaxf(acc[0][j+1], acc[1][j+1]), fmaxf(acc[2][j+1], acc[3][j+1])) + s_b1[c0+j+1], 0.0f);
            *(float2*)(hb + j) = v;
        }
    }

    // ---- phase B: conv2 + relu + pool -> g_feat (per-ky w2 slice staging) ----
    // 200 units: cg = t/50 (co-group of 16 -> warp-uniform => w broadcast),
    //            cell = t%50 (consecutive cells in warp, stride 34 => conflict-free)
    const bool active = t < 200;
    const int cg   = t / 50;
    const int cell = t - cg * 50;
    const int co0  = cg * 16;
    const int img  = cell / 25;
    const int c25  = cell - img * 25;
    const int qy = c25 / 5, qx = c25 - qy * 5;
    const float* hb = s_h + img * (169 * HS);

    float acc[4][16];
    #pragma unroll
    for (int p = 0; p < 4; p++)
        #pragma unroll
        for (int j = 0; j < 16; j++) acc[p][j] = 0.0f;

    for (int ky = 0; ky < 3; ky++) {
        __syncthreads();
        // stage w2 slice for this ky: [3 kx][32 ci][64 co] = 6144 floats, coalesced
        {
            const float4* src = (const float4*)(w2 + ky * 6144);
            float4* dst = (float4*)s_w2;
            for (int i = t; i < 1536; i += NT) dst[i] = src[i];
        }
        __syncthreads();

        if (active) {
            #pragma unroll 1
            for (int kx = 0; kx < 3; kx++) {
                const float* hp = hb + ((2 * qy + ky) * 13 + (2 * qx + kx)) * HS;
                const float* wt = s_w2 + kx * 2048 + co0;

                #pragma unroll 2
                for (int ci = 0; ci < 32; ci += 2) {
                    const float2 h0 = *(const float2*)(hp + ci);
                    const float2 h1 = *(const float2*)(hp + HS + ci);
                    const float2 h2 = *(const float2*)(hp + 13 * HS + ci);
                    const float2 h3 = *(const float2*)(hp + 14 * HS + ci);
                    const float* wp = wt + ci * 64;

                    float4 w4[4];
                    #pragma unroll
                    for (int jj = 0; jj < 4; jj++) w4[jj] = *(const float4*)(wp + 4 * jj);
                    {
                        const float hv[4] = { h0.x, h1.x, h2.x, h3.x };
                        #pragma unroll
                        for (int p = 0; p < 4; p++) {
                            const float hx = hv[p];
                            #pragma unroll
                            for (int jj = 0; jj < 4; jj++) {
                                acc[p][4*jj+0] = fmaf(hx, w4[jj].x, acc[p][4*jj+0]);
                                acc[p][4*jj+1] = fmaf(hx, w4[jj].y, acc[p][4*jj+1]);
                                acc[p][4*jj+2] = fmaf(hx, w4[jj].z, acc[p][4*jj+2]);
                                acc[p][4*jj+3] = fmaf(hx, w4[jj].w, acc[p][4*jj+3]);
                            }
                        }
                    }
                    #pragma unroll
                    for (int jj = 0; jj < 4; jj++) w4[jj] = *(const float4*)(wp + 64 + 4 * jj);
                    {
                        const float hv[4] = { h0.y, h1.y, h2.y, h3.y };
                        #pragma unroll
                        for (int p = 0; p < 4; p++) {
                            const float hx = hv[p];
                            #pragma unroll
                            for (int jj = 0; jj < 4; jj++) {
                                acc[p][4*jj+0] = fmaf(hx, w4[jj].x, acc[p][4*jj+0]);
                                acc[p][4*jj+1] = fmaf(hx, w4[jj].y, acc[p][4*jj+1]);
                                acc[p][4*jj+2] = fmaf(hx, w4[jj].z, acc[p][4*jj+2]);
                                acc[p][4*jj+3] = fmaf(hx, w4[jj].w, acc[p][4*jj+3]);
                            }
                        }
                    }
                }
            }
        }
    }

    if (active) {
        const int b = b0 + img;
        float* fo = g_feat + (b * 25 + c25) * 64 + co0;
        #pragma unroll
        for (int j = 0; j < 16; j++) {
            float m = fmaxf(fmaxf(acc[0][j], acc[1][j]), fmaxf(acc[2][j], acc[3][j]));
            fo[j] = fmaxf(m + s_b2[co0 + j], 0.0f);
        }
    }
}

// ==================== K2: batched head GEMM + MoE epilogue ====================
// 256 blocks x 32 rows; [B,1600] x [1600,56]; 256 threads: 64 units (4rows x 7cols) x 4-way k-split
// smem aliasing: s_buf holds {s_f[2080] | s_w[3584]} during mainloop, then s_p[5376] after.
#define KC 64
__global__ __launch_bounds__(256) void moe_head_kernel(
    const float* __restrict__ gw,   // [1600,5]
    const float* __restrict__ gb,   // [5]
    const float* __restrict__ ew,   // [5,1600,10]
    const float* __restrict__ eb,   // [5,10]
    float* __restrict__ out)        // [B,10]
{
    __shared__ float s_buf[5664];           // s_f[0..2080) | s_w[2080..5664) ; later s_p[0..5376)
    __shared__ float s_l[32 * 57];          // logits
    __shared__ float s_bias[56];

    float* s_f = s_buf;                     // [32][65]
    float* s_w = s_buf + 2080;              // [KC][56]
    float* s_p = s_buf;                     // [3][64][28] partials (after mainloop)

    const int t    = threadIdx.x;
    const int s    = t >> 6;        // k-split 0..3
    const int u    = t & 63;        // unit
    const int rg   = u >> 3;        // row group 0..7 -> rows rg*4..rg*4+3
    const int cgq  = u & 7;         // col group 0..7 -> cols cgq*7..cgq*7+6
    const int r0   = rg * 4;
    const int cb   = cgq * 7;
    const int row0 = blockIdx.x * 32;
    const int kk0  = s * 16;

    if (t < 56) s_bias[t] = (t < 5) ? gb[t] : eb[t - 5];

    float acc[4][7];
    #pragma unroll
    for (int i = 0; i < 4; i++)
        #pragma unroll
        for (int j = 0; j < 7; j++) acc[i][j] = 0.0f;

    for (int chunk = 0; chunk < 25; chunk++) {
        const int k0 = chunk * KC;
        __syncthreads();
        // stage feat rows (coalesced)
        for (int i = t; i < 32 * KC; i += 256) {
            const int r = i >> 6, c = i & 63;
            s_f[r * 65 + c] = g_feat[(row0 + r) * 1600 + k0 + c];
        }
        // stage packed weights (gather gate+experts)
        for (int i = t; i < KC * 56; i += 256) {
            const int kkl = i / 56, j = i - kkl * 56;
            const int d = k0 + kkl;
            float v;
            if (j < 5) v = gw[d * 5 + j];
            else {
                const int e = (j - 5) / 10, c = (j - 5) % 10;
                v = ew[(e * 1600 + d) * 10 + c];
            }
            s_w[i] = v;
        }
        __syncthreads();

        #pragma unroll 4
        for (int kk = kk0; kk < kk0 + 16; kk++) {
            const float f0 = s_f[(r0    ) * 65 + kk];
            const float f1 = s_f[(r0 + 1) * 65 + kk];
            const float f2 = s_f[(r0 + 2) * 65 + kk];
            const float f3 = s_f[(r0 + 3) * 65 + kk];
            const float* wr = s_w + kk * 56 + cb;
            #pragma unroll
            for (int j = 0; j < 7; j++) {
                const float wv = wr[j];
                acc[0][j] = fmaf(f0, wv, acc[0][j]);
                acc[1][j] = fmaf(f1, wv, acc[1][j]);
                acc[2][j] = fmaf(f2, wv, acc[2][j]);
                acc[3][j] = fmaf(f3, wv, acc[3][j]);
            }
        }
    }

    // ---- k-split reduction (s_p aliases s_f/s_w -> barrier first) ----
    __syncthreads();
    if (s > 0) {
        float* pp = s_p + ((s - 1) * 64 + u) * 28;
        #pragma unroll
        for (int i = 0; i < 4; i++)
            #pragma unroll
            for (int j = 0; j < 7; j++) pp[i * 7 + j] = acc[i][j];
    }
    __syncthreads();
    if (s == 0) {
        #pragma unroll
        for (int q = 0; q < 3; q++) {
            const float* pp = s_p + (q * 64 + u) * 28;
            #pragma unroll
            for (int i = 0; i < 4; i++)
                #pragma unroll
                for (int j = 0; j < 7; j++) acc[i][j] += pp[i * 7 + j];
        }
        #pragma unroll
        for (int i = 0; i < 4; i++)
            #pragma unroll
            for (int j = 0; j < 7; j++)
                s_l[(r0 + i) * 57 + cb + j] = acc[i][j] + s_bias[cb + j];
    }
    __syncthreads();

    // per-row MoE epilogue
    if (t < 32) {
        const float* L = s_l + t * 57;
        float p[5];
        float gm = -1e30f;
        #pragma unroll
        for (int e = 0; e < 5; e++) gm = fmaxf(gm, L[e]);
        float gsum = 0.0f;
        #pragma unroll
        for (int e = 0; e < 5; e++) { p[e] = expf(L[e] - gm); gsum += p[e]; }
        const float ginv = 1.0f / gsum;
        #pragma unroll
        for (int e = 0; e < 5; e++) p[e] *= ginv;

        int idx[5] = {0, 1, 2, 3, 4};
        #pragma unroll
        for (int a = 0; a < 3; a++) {
            int best = a;
            #pragma unroll
            for (int q = a + 1; q < 5; q++)
                if (p[idx[q]] > p[idx[best]]) best = q;
            const int tmp = idx[a]; idx[a] = idx[best]; idx[best] = tmp;
        }

        float comb[10];
        #pragma unroll
        for (int c = 0; c < 10; c++) {
            float v = 0.0f;
            #pragma unroll
            for (int k = 0; k < 3; k++)
                v = fmaf(p[idx[k]], L[5 + idx[k] * 10 + c], v);
            comb[c] = v;
        }
        float cm = -1e30f;
        #pragma unroll
        for (int c = 0; c < 10; c++) cm = fmaxf(cm, comb[c]);
        float cs = 0.0f;
        float ex[10];
        #pragma unroll
        for (int c = 0; c < 10; c++) { ex[c] = expf(comb[c] - cm); cs += ex[c]; }
        const float inv = 1.0f / cs;
        float* o = out + (row0 + t) * 10;
        #pragma unroll
        for (int c = 0; c < 10; c++) o[c] = ex[c] * inv;
    }
}

// ==================== launcher ====================
extern "C" void kernel_launch(void* const* d_in, const int* in_sizes, int n_in,
                              void* d_out, int out_size) {
    const float* x  = (const float*)d_in[0];
    const float* w1 = (const float*)d_in[1];
    const float* b1 = (const float*)d_in[2];
    const float* w2 = (const float*)d_in[3];
    const float* b2 = (const float*)d_in[4];
    const float* gw = (const float*)d_in[5];
    const float* gb = (const float*)d_in[6];
    const float* ew = (const float*)d_in[7];
    const float* eb = (const float*)d_in[8];
    float* out = (float*)d_out;

    const size_t smem_bytes = SME_FLOATS * sizeof(float);
    cudaFuncSetAttribute(conv_fused_kernel,
                         cudaFuncAttributeMaxDynamicSharedMemorySize, (int)smem_bytes);

    conv_fused_kernel<<<NBLK, NT, smem_bytes>>>(x, w1, b1, w2, b2);
    moe_head_kernel<<<B / 32, 256>>>(gw, gb, ew, eb, out);
}

// round 7
// speedup vs baseline: 1.8847x; 1.2515x over previous
#include <cuda_runtime.h>
#include <math.h>

#define B        8192
#define IMG_PB   2
#define NBLK     (B / IMG_PB)     // 4096
#define NT       256

// h1 pooled output stride per (row,col) cell: 34 floats (32 ch + 2 pad) -> bank spread
#define HS 34

typedef unsigned long long ull;

// ---------------- packed f32x2 helpers (Blackwell FFMA2 path) ----------------
__device__ __forceinline__ ull pack2(float v) {
    ull r;
    asm("mov.b64 %0, {%1, %1};" : "=l"(r) : "f"(v));
    return r;
}
__device__ __forceinline__ void fma2(ull& d, ull a, ull b) {
    asm("fma.rn.f32x2 %0, %1, %2, %0;" : "+l"(d) : "l"(a), "l"(b));
}
__device__ __forceinline__ float2 unpack2(ull v) {
    float2 f;
    asm("mov.b64 {%0, %1}, %2;" : "=f"(f.x), "=f"(f.y) : "l"(v));
    return f;
}

// ---------------- global scratch (no allocs allowed) ----------------
__device__ float g_feat[B * 1600];        // [B][25cells][64co]
__device__ float g_wpack[1600 * 56];      // [d][j]: j<5 gate, 5..54 experts, 55 pad

// ==================== K0: pack gate+expert weights ====================
__global__ void pack_weights_kernel(const float* __restrict__ gw,
                                    const float* __restrict__ ew) {
    int i = blockIdx.x * blockDim.x + threadIdx.x;
    if (i >= 1600 * 56) return;
    int d = i / 56, j = i - d * 56;
    float v = 0.0f;
    if (j < 5)       v = gw[d * 5 + j];
    else if (j < 55) {
        int e = (j - 5) / 10, c = (j - 5) % 10;
        v = ew[(e * 1600 + d) * 10 + c];
    }
    g_wpack[i] = v;
}

// ==================== K1: conv1+pool + conv2+pool (2 images / block) ====================
// dyn smem (floats): s_h 2*169*34=11492 | s_w2 slice 6144 | s_x 1568 | s_w1 288 | s_b1 32 | s_b2 64
#define SME_FLOATS (11492 + 6144 + 1568 + 288 + 32 + 64)

__global__ __launch_bounds__(NT, 2) void conv_fused_kernel(
    const float* __restrict__ x,    // [B,28,28,1]
    const float* __restrict__ w1,   // [3,3,1,32]
    const float* __restrict__ b1,   // [32]
    const float* __restrict__ w2,   // [3,3,32,64] = 18432 floats
    const float* __restrict__ b2)   // [64]
{
    extern __shared__ float sm[];
    float* s_h  = sm;                       // [2*169][34]
    float* s_w2 = s_h + 11492;              // one ky slice: [3 kx][32 ci][64 co] = 6144
    float* s_x  = s_w2 + 6144;              // [2][784]
    float* s_w1 = s_x + 1568;               // [9 taps][32]
    float* s_b1 = s_w1 + 288;
    float* s_b2 = s_b1 + 32;

    const int t  = threadIdx.x;
    const int b0 = blockIdx.x * IMG_PB;

    // ---- stage x, w1, biases ----
    {
        const float* xi = x + b0 * 784;
        for (int i = t; i < 1568; i += NT) s_x[i] = xi[i];
        for (int i = t; i < 288; i += NT) s_w1[i] = w1[i];
        if (t < 32) s_b1[t] = b1[t];
        if (t < 64) s_b2[t] = b2[t];
    }
    __syncthreads();

    // ---- phase A: conv1 + relu + pool -> s_h (stride HS), packed f32x2 ----
    for (int i = t; i < 1352; i += NT) {
        const int img  = i / 676;
        const int r    = i - img * 676;
        const int cell = r >> 2;
        const int c0   = (r & 3) * 8;
        const int qy = cell / 13, qx = cell - qy * 13;
        const float* xb = s_x + img * 784 + (2 * qy) * 28 + 2 * qx;

        ull a1[4][4];                       // 4 pos x 4 co-pairs (8 co)
        #pragma unroll
        for (int p = 0; p < 4; p++)
            #pragma unroll
            for (int j = 0; j < 4; j++) a1[p][j] = 0ULL;

        #pragma unroll
        for (int ky = 0; ky < 3; ky++) {
            #pragma unroll
            for (int kx = 0; kx < 3; kx++) {
                const float* xp = xb + ky * 28 + kx;
                const ull xpk[4] = { pack2(xp[0]), pack2(xp[1]),
                                     pack2(xp[28]), pack2(xp[29]) };
                const ulonglong2* wq = (const ulonglong2*)(s_w1 + (ky * 3 + kx) * 32 + c0);
                const ulonglong2 wA = wq[0], wB = wq[1];
                const ull wv[4] = { wA.x, wA.y, wB.x, wB.y };
                #pragma unroll
                for (int p = 0; p < 4; p++)
                    #pragma unroll
                    for (int j = 0; j < 4; j++)
                        fma2(a1[p][j], xpk[p], wv[j]);
            }
        }
        float* hb = s_h + (img * 169 + cell) * HS + c0;
        #pragma unroll
        for (int j = 0; j < 4; j++) {        // pair j -> co 2j, 2j+1
            const float2 u0 = unpack2(a1[0][j]);
            const float2 u1 = unpack2(a1[1][j]);
            const float2 u2 = unpack2(a1[2][j]);
            const float2 u3 = unpack2(a1[3][j]);
            float2 v;
            v.x = fmaxf(fmaxf(fmaxf(u0.x, u1.x), fmaxf(u2.x, u3.x)) + s_b1[c0 + 2*j],     0.0f);
            v.y = fmaxf(fmaxf(fmaxf(u0.y, u1.y), fmaxf(u2.y, u3.y)) + s_b1[c0 + 2*j + 1], 0.0f);
            *(float2*)(hb + 2*j) = v;
        }
    }

    // ---- phase B: conv2 + relu + pool -> g_feat (per-ky w2 slice, packed f32x2) ----
    // 200 units: cg = t/50 (co-group of 16, warp-uniform => w LDS broadcast),
    //            cell = t%50 (consecutive cells, stride 34 => conflict-free h loads)
    const bool active = t < 200;
    const int cg   = t / 50;
    const int cell = t - cg * 50;
    const int co0  = cg * 16;
    const int img  = cell / 25;
    const int c25  = cell - img * 25;
    const int qy = c25 / 5, qx = c25 - qy * 5;
    const float* hb = s_h + img * (169 * HS);

    ull a2[4][8];                           // 4 pos x 8 co-pairs (16 co)
    #pragma unroll
    for (int p = 0; p < 4; p++)
        #pragma unroll
        for (int j = 0; j < 8; j++) a2[p][j] = 0ULL;

    for (int ky = 0; ky < 3; ky++) {
        __syncthreads();
        // stage w2 slice for this ky: [3 kx][32 ci][64 co] = 6144 floats, coalesced
        {
            const float4* src = (const float4*)(w2 + ky * 6144);
            float4* dst = (float4*)s_w2;
            for (int i = t; i < 1536; i += NT) dst[i] = src[i];
        }
        __syncthreads();

        if (active) {
            #pragma unroll 1
            for (int kx = 0; kx < 3; kx++) {
                const float* hp = hb + ((2 * qy + ky) * 13 + (2 * qx + kx)) * HS;
                const float* wt = s_w2 + kx * 2048 + co0;

                #pragma unroll 2
                for (int ci = 0; ci < 32; ci += 2) {
                    const float2 h0 = *(const float2*)(hp + ci);
                    const float2 h1 = *(const float2*)(hp + HS + ci);
                    const float2 h2 = *(const float2*)(hp + 13 * HS + ci);
                    const float2 h3 = *(const float2*)(hp + 14 * HS + ci);

                    // ci even half
                    {
                        const ulonglong2* wq = (const ulonglong2*)(wt + ci * 64);
                        const ulonglong2 wa = wq[0], wb = wq[1], wc = wq[2], wd = wq[3];
                        const ull wv[8] = { wa.x, wa.y, wb.x, wb.y, wc.x, wc.y, wd.x, wd.y };
                        const ull hpk[4] = { pack2(h0.x), pack2(h1.x), pack2(h2.x), pack2(h3.x) };
                        #pragma unroll
                        for (int p = 0; p < 4; p++)
                            #pragma unroll
                            for (int j = 0; j < 8; j++)
                                fma2(a2[p][j], hpk[p], wv[j]);
                    }
                    // ci odd half
                    {
                        const ulonglong2* wq = (const ulonglong2*)(wt + ci * 64 + 64);
                        const ulonglong2 wa = wq[0], wb = wq[1], wc = wq[2], wd = wq[3];
                        const ull wv[8] = { wa.x, wa.y, wb.x, wb.y, wc.x, wc.y, wd.x, wd.y };
                        const ull hpk[4] = { pack2(h0.y), pack2(h1.y), pack2(h2.y), pack2(h3.y) };
                        #pragma unroll
                        for (int p = 0; p < 4; p++)
                            #pragma unroll
                            for (int j = 0; j < 8; j++)
                                fma2(a2[p][j], hpk[p], wv[j]);
                    }
                }
            }
        }
    }

    if (active) {
        const int b = b0 + img;
        float* fo = g_feat + (b * 25 + c25) * 64 + co0;
        #pragma unroll
        for (int j = 0; j < 8; j++) {        // pair j -> co 2j, 2j+1
            const float2 u0 = unpack2(a2[0][j]);
            const float2 u1 = unpack2(a2[1][j]);
            const float2 u2 = unpack2(a2[2][j]);
            const float2 u3 = unpack2(a2[3][j]);
            float2 v;
            v.x = fmaxf(fmaxf(fmaxf(u0.x, u1.x), fmaxf(u2.x, u3.x)) + s_b2[co0 + 2*j],     0.0f);
            v.y = fmaxf(fmaxf(fmaxf(u0.y, u1.y), fmaxf(u2.y, u3.y)) + s_b2[co0 + 2*j + 1], 0.0f);
            *(float2*)(fo + 2*j) = v;
        }
    }
}

// ==================== K2: batched head GEMM + MoE epilogue ====================
// 256 blocks x 32 rows; [B,1600] x [1600,56packed]; 64 units (4rows x 7cols) x 4-way k-split
// smem aliasing: s_buf holds {s_f[2080] | s_w[3584]} during mainloop, then s_p[5376] after.
#define KC 64
__global__ __launch_bounds__(256) void moe_head_kernel(
    const float* __restrict__ gb,   // [5]
    const float* __restrict__ eb,   // [5,10]
    float* __restrict__ out)        // [B,10]
{
    __shared__ float s_buf[5664];           // s_f[0..2080) | s_w[2080..5664) ; later s_p[0..5376)
    __shared__ float s_l[32 * 57];          // logits
    __shared__ float s_bias[56];

    float* s_f = s_buf;                     // [32][65]
    float* s_w = s_buf + 2080;              // [KC][56]
    float* s_p = s_buf;                     // [3][64][28] partials (after mainloop)

    const int t    = threadIdx.x;
    const int s    = t >> 6;        // k-split 0..3
    const int u    = t & 63;        // unit
    const int rg   = u >> 3;        // row group -> rows rg*4..rg*4+3
    const int cgq  = u & 7;         // col group -> cols cgq*7..cgq*7+6
    const int r0   = rg * 4;
    const int cb   = cgq * 7;
    const int row0 = blockIdx.x * 32;
    const int kk0  = s * 16;

    if (t < 56) s_bias[t] = (t < 5) ? gb[t] : eb[t - 5];

    float acc[4][7];
    #pragma unroll
    for (int i = 0; i < 4; i++)
        #pragma unroll
        for (int j = 0; j < 7; j++) acc[i][j] = 0.0f;

    for (int chunk = 0; chunk < 25; chunk++) {
        const int k0 = chunk * KC;
        __syncthreads();
        // stage feat rows (coalesced)
        for (int i = t; i < 32 * KC; i += 256) {
            const int r = i >> 6, c = i & 63;
            s_f[r * 65 + c] = g_feat[(row0 + r) * 1600 + k0 + c];
        }
        // stage packed weights: pure float4 copy (KC*56 = 3584 floats = 896 float4)
        {
            const float4* src = (const float4*)(g_wpack + k0 * 56);
            float4* dst = (float4*)s_w;
            for (int i = t; i < 896; i += 256) dst[i] = src[i];
        }
        __syncthreads();

        #pragma unroll 4
        for (int kk = kk0; kk < kk0 + 16; kk++) {
            const float f0 = s_f[(r0    ) * 65 + kk];
            const float f1 = s_f[(r0 + 1) * 65 + kk];
            const float f2 = s_f[(r0 + 2) * 65 + kk];
            const float f3 = s_f[(r0 + 3) * 65 + kk];
            const float* wr = s_w + kk * 56 + cb;
            #pragma unroll
            for (int j = 0; j < 7; j++) {
                const float wv = wr[j];
                acc[0][j] = fmaf(f0, wv, acc[0][j]);
                acc[1][j] = fmaf(f1, wv, acc[1][j]);
                acc[2][j] = fmaf(f2, wv, acc[2][j]);
                acc[3][j] = fmaf(f3, wv, acc[3][j]);
            }
        }
    }

    // ---- k-split reduction (s_p aliases s_f/s_w -> barrier first) ----
    __syncthreads();
    if (s > 0) {
        float* pp = s_p + ((s - 1) * 64 + u) * 28;
        #pragma unroll
        for (int i = 0; i < 4; i++)
            #pragma unroll
            for (int j = 0; j < 7; j++) pp[i * 7 + j] = acc[i][j];
    }
    __syncthreads();
    if (s == 0) {
        #pragma unroll
        for (int q = 0; q < 3; q++) {
            const float* pp = s_p + (q * 64 + u) * 28;
            #pragma unroll
            for (int i = 0; i < 4; i++)
                #pragma unroll
                for (int j = 0; j < 7; j++) acc[i][j] += pp[i * 7 + j];
        }
        #pragma unroll
        for (int i = 0; i < 4; i++)
            #pragma unroll
            for (int j = 0; j < 7; j++)
                s_l[(r0 + i) * 57 + cb + j] = acc[i][j] + s_bias[cb + j];
    }
    __syncthreads();

    // per-row MoE epilogue
    if (t < 32) {
        const float* L = s_l + t * 57;
        float p[5];
        float gm = -1e30f;
        #pragma unroll
        for (int e = 0; e < 5; e++) gm = fmaxf(gm, L[e]);
        float gsum = 0.0f;
        #pragma unroll
        for (int e = 0; e < 5; e++) { p[e] = expf(L[e] - gm); gsum += p[e]; }
        const float ginv = 1.0f / gsum;
        #pragma unroll
        for (int e = 0; e < 5; e++) p[e] *= ginv;

        int idx[5] = {0, 1, 2, 3, 4};
        #pragma unroll
        for (int a = 0; a < 3; a++) {
            int best = a;
            #pragma unroll
            for (int q = a + 1; q < 5; q++)
                if (p[idx[q]] > p[idx[best]]) best = q;
            const int tmp = idx[a]; idx[a] = idx[best]; idx[best] = tmp;
        }

        float comb[10];
        #pragma unroll
        for (int c = 0; c < 10; c++) {
            float v = 0.0f;
            #pragma unroll
            for (int k = 0; k < 3; k++)
                v = fmaf(p[idx[k]], L[5 + idx[k] * 10 + c], v);
            comb[c] = v;
        }
        float cm = -1e30f;
        #pragma unroll
        for (int c = 0; c < 10; c++) cm = fmaxf(cm, comb[c]);
        float cs = 0.0f;
        float ex[10];
        #pragma unroll
        for (int c = 0; c < 10; c++) { ex[c] = expf(comb[c] - cm); cs += ex[c]; }
        const float inv = 1.0f / cs;
        float* o = out + (row0 + t) * 10;
        #pragma unroll
        for (int c = 0; c < 10; c++) o[c] = ex[c] * inv;
    }
}

// ==================== launcher ====================
extern "C" void kernel_launch(void* const* d_in, const int* in_sizes, int n_in,
                              void* d_out, int out_size) {
    const float* x  = (const float*)d_in[0];
    const float* w1 = (const float*)d_in[1];
    const float* b1 = (const float*)d_in[2];
    const float* w2 = (const float*)d_in[3];
    const float* b2 = (const float*)d_in[4];
    const float* gw = (const float*)d_in[5];
    const float* gb = (const float*)d_in[6];
    const float* ew = (const float*)d_in[7];
    const float* eb = (const float*)d_in[8];
    float* out = (float*)d_out;

    const size_t smem_bytes = SME_FLOATS * sizeof(float);
    cudaFuncSetAttribute(conv_fused_kernel,
                         cudaFuncAttributeMaxDynamicSharedMemorySize, (int)smem_bytes);

    pack_weights_kernel<<<(1600 * 56 + 255) / 256, 256>>>(gw, ew);
    conv_fused_kernel<<<NBLK, NT, smem_bytes>>>(x, w1, b1, w2, b2);
    moe_head_kernel<<<B / 32, 256>>>(gb, eb, out);
}

// round 9
// speedup vs baseline: 2.6723x; 1.4179x over previous
#include <cuda_runtime.h>
#include <cuda_bf16.h>
#include <math.h>
#include <cstdint>

#define B 8192
#define NBLK 4096      // 2 images per block

typedef unsigned long long ull;

// ---------------- packed f32x2 helpers ----------------
__device__ __forceinline__ ull pack2(float v) {
    ull r; asm("mov.b64 %0, {%1, %1};" : "=l"(r) : "f"(v)); return r;
}
__device__ __forceinline__ void fma2(ull& d, ull a, ull b) {
    asm("fma.rn.f32x2 %0, %1, %2, %0;" : "+l"(d) : "l"(a), "l"(b));
}
__device__ __forceinline__ float2 unpack2(ull v) {
    float2 f; asm("mov.b64 {%0, %1}, %2;" : "=f"(f.x), "=f"(f.y) : "l"(v)); return f;
}

// ---------------- bf16 pack helpers ----------------
// result: lo half = convert(lo), hi half = convert(hi)
__device__ __forceinline__ uint32_t bfpack(float lo, float hi) {
    uint32_t r;
    asm("cvt.rn.bf16x2.f32 %0, %1, %2;" : "=r"(r) : "f"(hi), "f"(lo));
    return r;
}
// residual (v - widen(hi_pair)) packed to bf16x2
__device__ __forceinline__ uint32_t bflo(float2 v, uint32_t hipk) {
    const float w0 = __uint_as_float(hipk << 16);
    const float w1 = __uint_as_float(hipk & 0xFFFF0000u);
    return bfpack(v.x - w0, v.y - w1);
}

// ---------------- mma.sync m16n8k16 bf16 (sm_80+, valid on plain sm_100) ----------------
__device__ __forceinline__ void mma_bf16(float* c, const uint32_t* a, const uint32_t* b) {
    asm volatile(
        "mma.sync.aligned.m16n8k16.row.col.f32.bf16.bf16.f32 "
        "{%0,%1,%2,%3}, {%4,%5,%6,%7}, {%8,%9}, {%0,%1,%2,%3};"
        : "+f"(c[0]), "+f"(c[1]), "+f"(c[2]), "+f"(c[3])
        : "r"(a[0]), "r"(a[1]), "r"(a[2]), "r"(a[3]), "r"(b[0]), "r"(b[1]));
}

// ---------------- global scratch ----------------
__device__ float g_feat[B * 1600];
__device__ float g_wpack[1600 * 56];
#define WTS 296                                   // bf16 row stride for w2^T
__device__ __align__(16) __nv_bfloat16 g_wth[64 * WTS];
__device__ __align__(16) __nv_bfloat16 g_wtl[64 * WTS];

// ==================== prep: pack head weights ====================
__global__ void pack_weights_kernel(const float* __restrict__ gw,
                                    const float* __restrict__ ew) {
    int i = blockIdx.x * blockDim.x + threadIdx.x;
    if (i >= 1600 * 56) return;
    int d = i / 56, j = i - d * 56;
    float v = 0.0f;
    if (j < 5)       v = gw[d * 5 + j];
    else if (j < 55) {
        int e = (j - 5) / 10, c = (j - 5) % 10;
        v = ew[(e * 1600 + d) * 10 + c];
    }
    g_wpack[i] = v;
}

// ==================== prep: w2 -> transposed bf16 hi/lo [co][k] ====================
__global__ void prep_w2t_kernel(const float* __restrict__ w2) {
    int i = blockIdx.x * blockDim.x + threadIdx.x;
    if (i >= 64 * WTS) return;
    int co = i / WTS, k = i - co * WTS;
    float v = (k < 288) ? w2[k * 64 + co] : 0.0f;
    __nv_bfloat16 h = __float2bfloat16_rn(v);
    __nv_bfloat16 l = __float2bfloat16_rn(v - __bfloat162float(h));
    g_wth[i] = h;
    g_wtl[i] = l;
}

// ==================== K1: conv1(FFMA2) + conv2(mma.sync bf16x3) ====================
// smem layout (bytes):
#define SM_H   0                       // 2*169*34 f32 = 45968
#define SM_WH  45968                   // 64*296 bf16 = 37888
#define SM_WL  83856                   // 37888
#define SM_X   121744                  // 2*784 f32 = 6272
#define SM_W1  128016                  // 288 f32 = 1152
#define SM_B1  129168                  // 32 f32
#define SM_B2  129296                  // 64 f32
#define SM_TOTAL 129552
#define SM_D   SM_WH                   // D [2][128][66] f32 = 67584, aliases WH+WL after mainloop
#define HSS 34

__global__ __launch_bounds__(256) void conv_mma_kernel(
    const float* __restrict__ x,
    const float* __restrict__ w1,
    const float* __restrict__ b1,
    const float* __restrict__ b2)
{
    extern __shared__ char smc[];
    float* s_h  = (float*)(smc + SM_H);
    float* s_x  = (float*)(smc + SM_X);
    float* s_w1 = (float*)(smc + SM_W1);
    float* s_b1 = (float*)(smc + SM_B1);
    float* s_b2 = (float*)(smc + SM_B2);
    const __nv_bfloat16* s_wh = (const __nv_bfloat16*)(smc + SM_WH);
    const __nv_bfloat16* s_wl = (const __nv_bfloat16*)(smc + SM_WL);
    float* s_D = (float*)(smc + SM_D);

    const int t   = threadIdx.x;
    const int wid = t >> 5;
    const int lane = t & 31;
    const int b0 = blockIdx.x * 2;

    // ---- stage x (2 imgs), w1, biases, w2t hi/lo ----
    {
        const float* xi = x + b0 * 784;
        for (int i = t; i < 1568; i += 256) s_x[i] = xi[i];
        for (int i = t; i < 288; i += 256) s_w1[i] = w1[i];
        if (t < 32) s_b1[t] = b1[t];
        else if (t < 96) s_b2[t - 32] = b2[t - 32];
        const float4* sh = (const float4*)g_wth;
        const float4* sl = (const float4*)g_wtl;
        float4* dh = (float4*)(smc + SM_WH);
        float4* dl = (float4*)(smc + SM_WL);
        for (int i = t; i < 2368; i += 256) { dh[i] = sh[i]; dl[i] = sl[i]; }
    }
    __syncthreads();

    // ---- conv1 + relu + pool -> s_h (FFMA2), both images ----
    for (int i = t; i < 1352; i += 256) {
        const int img  = i / 676;
        const int r    = i - img * 676;
        const int cell = r >> 2;
        const int c0   = (r & 3) * 8;
        const int qy = cell / 13, qx = cell - qy * 13;
        const float* xb = s_x + img * 784 + (2 * qy) * 28 + 2 * qx;

        ull a1[4][4];
        #pragma unroll
        for (int p = 0; p < 4; p++)
            #pragma unroll
            for (int j = 0; j < 4; j++) a1[p][j] = 0ULL;

        #pragma unroll
        for (int ky = 0; ky < 3; ky++)
            #pragma unroll
            for (int kx = 0; kx < 3; kx++) {
                const float* xp = xb + ky * 28 + kx;
                const ull xpk[4] = { pack2(xp[0]), pack2(xp[1]), pack2(xp[28]), pack2(xp[29]) };
                const ulonglong2* wq = (const ulonglong2*)(s_w1 + (ky * 3 + kx) * 32 + c0);
                const ulonglong2 wA = wq[0], wB = wq[1];
                const ull wv[4] = { wA.x, wA.y, wB.x, wB.y };
                #pragma unroll
                for (int p = 0; p < 4; p++)
                    #pragma unroll
                    for (int j = 0; j < 4; j++) fma2(a1[p][j], xpk[p], wv[j]);
            }
        float* hb = s_h + (img * 169 + cell) * HSS + c0;
        #pragma unroll
        for (int j = 0; j < 4; j++) {
            const float2 u0 = unpack2(a1[0][j]), u1 = unpack2(a1[1][j]);
            const float2 u2 = unpack2(a1[2][j]), u3 = unpack2(a1[3][j]);
            float2 v;
            v.x = fmaxf(fmaxf(fmaxf(u0.x, u1.x), fmaxf(u2.x, u3.x)) + s_b1[c0 + 2*j],     0.0f);
            v.y = fmaxf(fmaxf(fmaxf(u0.y, u1.y), fmaxf(u2.y, u3.y)) + s_b1[c0 + 2*j + 1], 0.0f);
            *(float2*)(hb + 2*j) = v;
        }
    }
    __syncthreads();

    // ---- conv2 GEMM: per image M=128 x N=64 x K=288, 4 warps/img (2 mtiles x 8 ntiles) ----
    const int img = wid >> 2;                 // 0..1
    const int wi  = wid & 3;                  // warp within image
    const int g   = lane >> 2;                // 0..7
    const int tq  = lane & 3;                 // 0..3
    const int rowbase = wi * 32;
    const float* himg = s_h + img * (169 * HSS);

    float acc[2][8][4];
    #pragma unroll
    for (int mt = 0; mt < 2; mt++)
        #pragma unroll
        for (int nt = 0; nt < 8; nt++)
            #pragma unroll
            for (int q = 0; q < 4; q++) acc[mt][nt][q] = 0.0f;

    #pragma unroll 1
    for (int ks = 0; ks < 18; ks++) {
        const int tap = ks >> 1;
        const int ty = tap / 3, tx = tap - ty * 3;
        const int toff = ty * 13 + tx;
        const int ci0 = (ks & 1) << 4;
        const int kb = ks * 16;

        // B fragments (shared by both mtiles): one u32 = bf16x2 over adjacent k
        uint32_t bh[8][2], bl[8][2];
        #pragma unroll
        for (int nt = 0; nt < 8; nt++) {
            const int co = nt * 8 + g;
            const uint32_t* ph = (const uint32_t*)(s_wh + co * WTS + kb);
            const uint32_t* pl = (const uint32_t*)(s_wl + co * WTS + kb);
            bh[nt][0] = ph[tq];     bh[nt][1] = ph[tq + 4];
            bl[nt][0] = pl[tq];     bl[nt][1] = pl[tq + 4];
        }

        #pragma unroll
        for (int mt = 0; mt < 2; mt++) {
            const int r0 = rowbase + mt * 16 + g + toff;
            const int r1 = r0 + 8;
            const int col = ci0 + 2 * tq;
            const float2 v00 = *(const float2*)(himg + r0 * HSS + col);
            const float2 v10 = *(const float2*)(himg + r1 * HSS + col);
            const float2 v01 = *(const float2*)(himg + r0 * HSS + col + 8);
            const float2 v11 = *(const float2*)(himg + r1 * HSS + col + 8);
            uint32_t ah[4], al[4];
            ah[0] = bfpack(v00.x, v00.y);  al[0] = bflo(v00, ah[0]);
            ah[1] = bfpack(v10.x, v10.y);  al[1] = bflo(v10, ah[1]);
            ah[2] = bfpack(v01.x, v01.y);  al[2] = bflo(v01, ah[2]);
            ah[3] = bfpack(v11.x, v11.y);  al[3] = bflo(v11, ah[3]);

            #pragma unroll
            for (int nt = 0; nt < 8; nt++) {
                mma_bf16(acc[mt][nt], ah, bh[nt]);   // Ah*Bh
                mma_bf16(acc[mt][nt], al, bh[nt]);   // Al*Bh
                mma_bf16(acc[mt][nt], ah, bl[nt]);   // Ah*Bl
            }
        }
    }

    // ---- write D to smem (aliases w buffers -> barrier first) ----
    __syncthreads();
    {
        float* Di = s_D + img * 8448;              // 128*66
        #pragma unroll
        for (int mt = 0; mt < 2; mt++) {
            const int r0 = rowbase + mt * 16 + g;
            #pragma unroll
            for (int nt = 0; nt < 8; nt++) {
                const int col = nt * 8 + 2 * tq;
                *(float2*)(Di + r0 * 66 + col)       = make_float2(acc[mt][nt][0], acc[mt][nt][1]);
                *(float2*)(Di + (r0 + 8) * 66 + col) = make_float2(acc[mt][nt][2], acc[mt][nt][3]);
            }
        }
    }
    __syncthreads();

    // ---- maxpool + bias + relu -> g_feat ----
    for (int u = t; u < 400; u += 256) {
        const int im = u / 200;
        const int r  = u - im * 200;
        const int cg = r / 25;
        const int pc = r - cg * 25;
        const int co0 = cg * 8;
        const int qy = pc / 5, qx = pc - qy * 5;
        const float* Di = s_D + im * 8448;
        const float* r0 = Di + (13 * (2 * qy)     + 2 * qx) * 66 + co0;
        const float* r1 = r0 + 66;
        const float* r2 = Di + (13 * (2 * qy + 1) + 2 * qx) * 66 + co0;
        const float* r3 = r2 + 66;
        float* fo = g_feat + ((b0 + im) * 25 + pc) * 64 + co0;
        #pragma unroll
        for (int j = 0; j < 8; j++) {
            const float m = fmaxf(fmaxf(r0[j], r1[j]), fmaxf(r2[j], r3[j]));
            fo[j] = fmaxf(m + s_b2[co0 + j], 0.0f);
        }
    }
}

// ==================== K2: batched head GEMM + MoE epilogue (R7, passing) ====================
#define KC 64
__global__ __launch_bounds__(256) void moe_head_kernel(
    const float* __restrict__ gb,
    const float* __restrict__ eb,
    float* __restrict__ out)
{
    __shared__ float s_buf[5664];
    __shared__ float s_l[32 * 57];
    __shared__ float s_bias[56];

    float* s_f = s_buf;
    float* s_w = s_buf + 2080;
    float* s_p = s_buf;

    const int t    = threadIdx.x;
    const int s    = t >> 6;
    const int u    = t & 63;
    const int rg   = u >> 3;
    const int cgq  = u & 7;
    const int r0   = rg * 4;
    const int cb   = cgq * 7;
    const int row0 = blockIdx.x * 32;
    const int kk0  = s * 16;

    if (t < 56) s_bias[t] = (t < 5) ? gb[t] : eb[t - 5];

    float acc[4][7];
    #pragma unroll
    for (int i = 0; i < 4; i++)
        #pragma unroll
        for (int j = 0; j < 7; j++) acc[i][j] = 0.0f;

    for (int chunk = 0; chunk < 25; chunk++) {
        const int k0 = chunk * KC;
        __syncthreads();
        for (int i = t; i < 32 * KC; i += 256) {
            const int r = i >> 6, c = i & 63;
            s_f[r * 65 + c] = g_feat[(row0 + r) * 1600 + k0 + c];
        }
        {
            const float4* src = (const float4*)(g_wpack + k0 * 56);
            float4* dst = (float4*)s_w;
            for (int i = t; i < 896; i += 256) dst[i] = src[i];
        }
        __syncthreads();

        #pragma unroll 4
        for (int kk = kk0; kk < kk0 + 16; kk++) {
            const float f0 = s_f[(r0    ) * 65 + kk];
            const float f1 = s_f[(r0 + 1) * 65 + kk];
            const float f2 = s_f[(r0 + 2) * 65 + kk];
            const float f3 = s_f[(r0 + 3) * 65 + kk];
            const float* wr = s_w + kk * 56 + cb;
            #pragma unroll
            for (int j = 0; j < 7; j++) {
                const float wv = wr[j];
                acc[0][j] = fmaf(f0, wv, acc[0][j]);
                acc[1][j] = fmaf(f1, wv, acc[1][j]);
                acc[2][j] = fmaf(f2, wv, acc[2][j]);
                acc[3][j] = fmaf(f3, wv, acc[3][j]);
            }
        }
    }

    __syncthreads();
    if (s > 0) {
        float* pp = s_p + ((s - 1) * 64 + u) * 28;
        #pragma unroll
        for (int i = 0; i < 4; i++)
            #pragma unroll
            for (int j = 0; j < 7; j++) pp[i * 7 + j] = acc[i][j];
    }
    __syncthreads();
    if (s == 0) {
        #pragma unroll
        for (int q = 0; q < 3; q++) {
            const float* pp = s_p + (q * 64 + u) * 28;
            #pragma unroll
            for (int i = 0; i < 4; i++)
                #pragma unroll
                for (int j = 0; j < 7; j++) acc[i][j] += pp[i * 7 + j];
        }
        #pragma unroll
        for (int i = 0; i < 4; i++)
            #pragma unroll
            for (int j = 0; j < 7; j++)
                s_l[(r0 + i) * 57 + cb + j] = acc[i][j] + s_bias[cb + j];
    }
    __syncthreads();

    if (t < 32) {
        const float* L = s_l + t * 57;
        float p[5];
        float gm = -1e30f;
        #pragma unroll
        for (int e = 0; e < 5; e++) gm = fmaxf(gm, L[e]);
        float gsum = 0.0f;
        #pragma unroll
        for (int e = 0; e < 5; e++) { p[e] = expf(L[e] - gm); gsum += p[e]; }
        const float ginv = 1.0f / gsum;
        #pragma unroll
        for (int e = 0; e < 5; e++) p[e] *= ginv;

        int idx[5] = {0, 1, 2, 3, 4};
        #pragma unroll
        for (int a = 0; a < 3; a++) {
            int best = a;
            #pragma unroll
            for (int q = a + 1; q < 5; q++)
                if (p[idx[q]] > p[idx[best]]) best = q;
            const int tmp = idx[a]; idx[a] = idx[best]; idx[best] = tmp;
        }

        float comb[10];
        #pragma unroll
        for (int c = 0; c < 10; c++) {
            float v = 0.0f;
            #pragma unroll
            for (int k = 0; k < 3; k++)
                v = fmaf(p[idx[k]], L[5 + idx[k] * 10 + c], v);
            comb[c] = v;
        }
        float cm = -1e30f;
        #pragma unroll
        for (int c = 0; c < 10; c++) cm = fmaxf(cm, comb[c]);
        float cs = 0.0f;
        float ex[10];
        #pragma unroll
        for (int c = 0; c < 10; c++) { ex[c] = expf(comb[c] - cm); cs += ex[c]; }
        const float inv = 1.0f / cs;
        float* o = out + (row0 + t) * 10;
        #pragma unroll
        for (int c = 0; c < 10; c++) o[c] = ex[c] * inv;
    }
}

// ==================== launcher ====================
extern "C" void kernel_launch(void* const* d_in, const int* in_sizes, int n_in,
                              void* d_out, int out_size) {
    const float* x  = (const float*)d_in[0];
    const float* w1 = (const float*)d_in[1];
    const float* b1 = (const float*)d_in[2];
    const float* w2 = (const float*)d_in[3];
    const float* b2 = (const float*)d_in[4];
    const float* gw = (const float*)d_in[5];
    const float* gb = (const float*)d_in[6];
    const float* ew = (const float*)d_in[7];
    const float* eb = (const float*)d_in[8];
    float* out = (float*)d_out;

    cudaFuncSetAttribute(conv_mma_kernel,
                         cudaFuncAttributeMaxDynamicSharedMemorySize, SM_TOTAL);

    pack_weights_kernel<<<(1600 * 56 + 255) / 256, 256>>>(gw, ew);
    prep_w2t_kernel<<<(64 * WTS + 255) / 256, 256>>>(w2);
    conv_mma_kernel<<<NBLK, 256, SM_TOTAL>>>(x, w1, b1, b2);
    moe_head_kernel<<<B / 32, 256>>>(gb, eb, out);
}

// round 10
// speedup vs baseline: 2.9125x; 1.0899x over previous
#include <cuda_runtime.h>
#include <cuda_bf16.h>
#include <math.h>
#include <cstdint>

#define B 8192

typedef unsigned long long ull;

// ---------------- packed f32x2 helpers ----------------
__device__ __forceinline__ ull pack2(float v) {
    ull r; asm("mov.b64 %0, {%1, %1};" : "=l"(r) : "f"(v)); return r;
}
__device__ __forceinline__ void fma2(ull& d, ull a, ull b) {
    asm("fma.rn.f32x2 %0, %1, %2, %0;" : "+l"(d) : "l"(a), "l"(b));
}
__device__ __forceinline__ float2 unpack2(ull v) {
    float2 f; asm("mov.b64 {%0, %1}, %2;" : "=f"(f.x), "=f"(f.y) : "l"(v)); return f;
}

// ---------------- bf16 pack helpers ----------------
__device__ __forceinline__ uint32_t bfpack(float lo, float hi) {
    uint32_t r;
    asm("cvt.rn.bf16x2.f32 %0, %1, %2;" : "=r"(r) : "f"(hi), "f"(lo));
    return r;
}
__device__ __forceinline__ uint32_t bflo(float2 v, uint32_t hipk) {
    const float w0 = __uint_as_float(hipk << 16);
    const float w1 = __uint_as_float(hipk & 0xFFFF0000u);
    return bfpack(v.x - w0, v.y - w1);
}

// ---------------- mma.sync m16n8k16 bf16 ----------------
__device__ __forceinline__ void mma_bf16(float* c, const uint32_t* a, const uint32_t* b) {
    asm volatile(
        "mma.sync.aligned.m16n8k16.row.col.f32.bf16.bf16.f32 "
        "{%0,%1,%2,%3}, {%4,%5,%6,%7}, {%8,%9}, {%0,%1,%2,%3};"
        : "+f"(c[0]), "+f"(c[1]), "+f"(c[2]), "+f"(c[3])
        : "r"(a[0]), "r"(a[1]), "r"(a[2]), "r"(a[3]), "r"(b[0]), "r"(b[1]));
}

// ---------------- global scratch ----------------
__device__ float g_feat[B * 1600];
__device__ float g_wpack[1600 * 56];
#define WTS 296
__device__ __align__(16) __nv_bfloat16 g_wth[64 * WTS];
__device__ __align__(16) __nv_bfloat16 g_wtl[64 * WTS];

// ==================== prep kernels ====================
__global__ void pack_weights_kernel(const float* __restrict__ gw,
                                    const float* __restrict__ ew) {
    int i = blockIdx.x * blockDim.x + threadIdx.x;
    if (i >= 1600 * 56) return;
    int d = i / 56, j = i - d * 56;
    float v = 0.0f;
    if (j < 5)       v = gw[d * 5 + j];
    else if (j < 55) {
        int e = (j - 5) / 10, c = (j - 5) % 10;
        v = ew[(e * 1600 + d) * 10 + c];
    }
    g_wpack[i] = v;
}

__global__ void prep_w2t_kernel(const float* __restrict__ w2) {
    int i = blockIdx.x * blockDim.x + threadIdx.x;
    if (i >= 64 * WTS) return;
    int co = i / WTS, k = i - co * WTS;
    float v = (k < 288) ? w2[k * 64 + co] : 0.0f;
    __nv_bfloat16 h = __float2bfloat16_rn(v);
    __nv_bfloat16 l = __float2bfloat16_rn(v - __bfloat162float(h));
    g_wth[i] = h;
    g_wtl[i] = l;
}

// ==================== K1: conv1(FFMA2) + conv2(mma.sync, M=112) — 1 image/block ====================
#define SM_H   0                       // 169*34 f32 = 22984 -> pad 22992
#define SM_WH  22992                   // 64*296 bf16 = 37888
#define SM_WL  60880
#define SM_X   98768                   // 784 f32 = 3136
#define SM_W1  101904                  // 288 f32
#define SM_B1  103056
#define SM_B2  103184
#define SM_TOTAL 103440
#define SM_D   SM_WH                   // D [112][66] f32 = 29568, aliases WH after mainloop
#define HSS 34

__global__ __launch_bounds__(256, 2) void conv_mma_kernel(
    const float* __restrict__ x,
    const float* __restrict__ w1,
    const float* __restrict__ b1,
    const float* __restrict__ b2)
{
    extern __shared__ char smc[];
    float* s_h  = (float*)(smc + SM_H);
    float* s_x  = (float*)(smc + SM_X);
    float* s_w1 = (float*)(smc + SM_W1);
    float* s_b1 = (float*)(smc + SM_B1);
    float* s_b2 = (float*)(smc + SM_B2);
    const __nv_bfloat16* s_wh = (const __nv_bfloat16*)(smc + SM_WH);
    const __nv_bfloat16* s_wl = (const __nv_bfloat16*)(smc + SM_WL);
    float* s_D = (float*)(smc + SM_D);

    const int t    = threadIdx.x;
    const int wid  = t >> 5;
    const int lane = t & 31;
    const int bb   = blockIdx.x;

    // ---- stage x, w1, biases, w2t hi/lo ----
    {
        const float* xi = x + bb * 784;
        for (int i = t; i < 784; i += 256) s_x[i] = xi[i];
        for (int i = t; i < 288; i += 256) s_w1[i] = w1[i];
        if (t < 32) s_b1[t] = b1[t];
        else if (t < 96) s_b2[t - 32] = b2[t - 32];
        const float4* sh = (const float4*)g_wth;
        const float4* sl = (const float4*)g_wtl;
        float4* dh = (float4*)(smc + SM_WH);
        float4* dl = (float4*)(smc + SM_WL);
        for (int i = t; i < 2368; i += 256) { dh[i] = sh[i]; dl[i] = sl[i]; }
    }
    __syncthreads();

    // ---- conv1 + relu + pool -> s_h (FFMA2) ----
    for (int i = t; i < 676; i += 256) {
        const int cell = i >> 2;
        const int c0   = (i & 3) * 8;
        const int qy = cell / 13, qx = cell - qy * 13;
        const float* xb = s_x + (2 * qy) * 28 + 2 * qx;

        ull a1[4][4];
        #pragma unroll
        for (int p = 0; p < 4; p++)
            #pragma unroll
            for (int j = 0; j < 4; j++) a1[p][j] = 0ULL;

        #pragma unroll
        for (int ky = 0; ky < 3; ky++)
            #pragma unroll
            for (int kx = 0; kx < 3; kx++) {
                const float* xp = xb + ky * 28 + kx;
                const ull xpk[4] = { pack2(xp[0]), pack2(xp[1]), pack2(xp[28]), pack2(xp[29]) };
                const ulonglong2* wq = (const ulonglong2*)(s_w1 + (ky * 3 + kx) * 32 + c0);
                const ulonglong2 wA = wq[0], wB = wq[1];
                const ull wv[4] = { wA.x, wA.y, wB.x, wB.y };
                #pragma unroll
                for (int p = 0; p < 4; p++)
                    #pragma unroll
                    for (int j = 0; j < 4; j++) fma2(a1[p][j], xpk[p], wv[j]);
            }
        float* hb = s_h + cell * HSS + c0;
        #pragma unroll
        for (int j = 0; j < 4; j++) {
            const float2 u0 = unpack2(a1[0][j]), u1 = unpack2(a1[1][j]);
            const float2 u2 = unpack2(a1[2][j]), u3 = unpack2(a1[3][j]);
            float2 v;
            v.x = fmaxf(fmaxf(fmaxf(u0.x, u1.x), fmaxf(u2.x, u3.x)) + s_b1[c0 + 2*j],     0.0f);
            v.y = fmaxf(fmaxf(fmaxf(u0.y, u1.y), fmaxf(u2.y, u3.y)) + s_b1[c0 + 2*j + 1], 0.0f);
            *(float2*)(hb + 2*j) = v;
        }
    }
    __syncthreads();

    // ---- conv2 GEMM: M=112 (rows = 100 needed cells + pad) x N=64 x K=288 ----
    // warp w (0..6) = m-tile w over all 8 n-tiles; warp 7 idle in mainloop.
    const int g  = lane >> 2;          // 0..7
    const int tq = lane & 3;           // 0..3

    float acc[8][4];
    #pragma unroll
    for (int nt = 0; nt < 8; nt++)
        #pragma unroll
        for (int q = 0; q < 4; q++) acc[nt][q] = 0.0f;

    // row -> h1 cell mapping (row r < 100 -> cell (r/10)*13 + r%10)
    const int r0 = wid * 16 + g;
    const int r1 = r0 + 8;
    const int crow0 = (r0 < 100) ? (r0 / 10) * 13 + (r0 % 10) : 0;
    const int crow1 = (r1 < 100) ? (r1 / 10) * 13 + (r1 % 10) : 0;

    if (wid < 7) {
        #pragma unroll 1
        for (int ks = 0; ks < 18; ks++) {
            const int tap = ks >> 1;
            const int ty = tap / 3, tx = tap - ty * 3;
            const int toff = ty * 13 + tx;
            const int ci0 = (ks & 1) << 4;
            const int kb = ks * 16;

            uint32_t bh[8][2], bl[8][2];
            #pragma unroll
            for (int nt = 0; nt < 8; nt++) {
                const int co = nt * 8 + g;
                const uint32_t* ph = (const uint32_t*)(s_wh + co * WTS + kb);
                const uint32_t* pl = (const uint32_t*)(s_wl + co * WTS + kb);
                bh[nt][0] = ph[tq];     bh[nt][1] = ph[tq + 4];
                bl[nt][0] = pl[tq];     bl[nt][1] = pl[tq + 4];
            }

            const int col = ci0 + 2 * tq;
            const float* hp0 = s_h + (crow0 + toff) * HSS + col;
            const float* hp1 = s_h + (crow1 + toff) * HSS + col;
            const float2 v00 = *(const float2*)(hp0);
            const float2 v10 = *(const float2*)(hp1);
            const float2 v01 = *(const float2*)(hp0 + 8);
            const float2 v11 = *(const float2*)(hp1 + 8);
            uint32_t ah[4], al[4];
            ah[0] = bfpack(v00.x, v00.y);  al[0] = bflo(v00, ah[0]);
            ah[1] = bfpack(v10.x, v10.y);  al[1] = bflo(v10, ah[1]);
            ah[2] = bfpack(v01.x, v01.y);  al[2] = bflo(v01, ah[2]);
            ah[3] = bfpack(v11.x, v11.y);  al[3] = bflo(v11, ah[3]);

            #pragma unroll
            for (int nt = 0; nt < 8; nt++) {
                mma_bf16(acc[nt], ah, bh[nt]);
                mma_bf16(acc[nt], al, bh[nt]);
                mma_bf16(acc[nt], ah, bl[nt]);
            }
        }
    }

    // ---- write D to smem (aliases WH -> barrier first) ----
    __syncthreads();
    if (wid < 7) {
        const int dr0 = wid * 16 + g;
        #pragma unroll
        for (int nt = 0; nt < 8; nt++) {
            const int col = nt * 8 + 2 * tq;
            *(float2*)(s_D + dr0 * 66 + col)       = make_float2(acc[nt][0], acc[nt][1]);
            *(float2*)(s_D + (dr0 + 8) * 66 + col) = make_float2(acc[nt][2], acc[nt][3]);
        }
    }
    __syncthreads();

    // ---- maxpool + bias + relu -> g_feat (rows r = y*10+x) ----
    if (t < 200) {
        const int cg = t / 25;
        const int pc = t - cg * 25;
        const int co0 = cg * 8;
        const int qy = pc / 5, qx = pc - qy * 5;
        const float* r0p = s_D + ((2 * qy) * 10 + 2 * qx) * 66 + co0;
        const float* r1p = r0p + 66;
        const float* r2p = s_D + ((2 * qy + 1) * 10 + 2 * qx) * 66 + co0;
        const float* r3p = r2p + 66;
        float* fo = g_feat + (bb * 25 + pc) * 64 + co0;
        #pragma unroll
        for (int j = 0; j < 8; j++) {
            const float m = fmaxf(fmaxf(r0p[j], r1p[j]), fmaxf(r2p[j], r3p[j]));
            fo[j] = fmaxf(m + s_b2[co0 + j], 0.0f);
        }
    }
}

// ==================== K2: head GEMM + MoE epilogue — 512 blocks x 16 rows, double-buffered ====================
#define KC 64
#define FS 68                          // s_f row stride
#define STG (16 * FS + KC * 56)        // 4672 floats per stage
__global__ __launch_bounds__(256) void moe_head_kernel(
    const float* __restrict__ gb,
    const float* __restrict__ eb,
    float* __restrict__ out)
{
    __shared__ float s_stage[2 * STG];     // 9344 floats
    __shared__ float s_l[16 * 57];
    __shared__ float s_bias[56];
    float* s_p = s_stage;                  // 3*64*14 = 2688 partials, alias stage0 after loop

    const int t    = threadIdx.x;
    const int s    = t >> 6;               // k-split 0..3 (16 k each)
    const int u    = t & 63;               // unit: 8 rowgroups(2 rows) x 8 colgroups(7)
    const int rg   = u >> 3;
    const int cb   = (u & 7) * 7;
    const int r0   = rg * 2;
    const int row0 = blockIdx.x * 16;
    const int kk0  = s * 16;

    if (t < 56) s_bias[t] = (t < 5) ? gb[t] : eb[t - 5];

    float acc[2][7];
    #pragma unroll
    for (int i = 0; i < 2; i++)
        #pragma unroll
        for (int j = 0; j < 7; j++) acc[i][j] = 0.0f;

    // stage loader: chunk -> buffer
    auto load_stage = [&](int chunk, float* buf) {
        const int k0 = chunk * KC;
        float* sf = buf;
        float* sw = buf + 16 * FS;
        // feat: 16 rows x 64 cols, thread -> one float4
        {
            const int r = t >> 4, c0 = (t & 15) * 4;
            const float4 v = *(const float4*)(g_feat + (row0 + r) * 1600 + k0 + c0);
            *(float4*)(sf + r * FS + c0) = v;
        }
        // weights: 896 float4
        {
            const float4* src = (const float4*)(g_wpack + k0 * 56);
            float4* dst = (float4*)sw;
            for (int i = t; i < 896; i += 256) dst[i] = src[i];
        }
    };

    load_stage(0, s_stage);
    __syncthreads();

    for (int chunk = 0; chunk < 25; chunk++) {
        float* cur = s_stage + (chunk & 1) * STG;
        if (chunk < 24) load_stage(chunk + 1, s_stage + ((chunk + 1) & 1) * STG);

        const float* sf = cur;
        const float* sw = cur + 16 * FS;
        #pragma unroll 4
        for (int kk = kk0; kk < kk0 + 16; kk++) {
            const float f0 = sf[(r0    ) * FS + kk];
            const float f1 = sf[(r0 + 1) * FS + kk];
            const float* wr = sw + kk * 56 + cb;
            #pragma unroll
            for (int j = 0; j < 7; j++) {
                const float wv = wr[j];
                acc[0][j] = fmaf(f0, wv, acc[0][j]);
                acc[1][j] = fmaf(f1, wv, acc[1][j]);
            }
        }
        __syncthreads();
    }

    // ---- k-split reduction (s_p aliases stage0; barrier above covers) ----
    if (s > 0) {
        float* pp = s_p + ((s - 1) * 64 + u) * 14;
        #pragma unroll
        for (int i = 0; i < 2; i++)
            #pragma unroll
            for (int j = 0; j < 7; j++) pp[i * 7 + j] = acc[i][j];
    }
    __syncthreads();
    if (s == 0) {
        #pragma unroll
        for (int q = 0; q < 3; q++) {
            const float* pp = s_p + (q * 64 + u) * 14;
            #pragma unroll
            for (int i = 0; i < 2; i++)
                #pragma unroll
                for (int j = 0; j < 7; j++) acc[i][j] += pp[i * 7 + j];
        }
        #pragma unroll
        for (int i = 0; i < 2; i++)
            #pragma unroll
            for (int j = 0; j < 7; j++)
                s_l[(r0 + i) * 57 + cb + j] = acc[i][j] + s_bias[cb + j];
    }
    __syncthreads();

    // per-row MoE epilogue
    if (t < 16) {
        const float* L = s_l + t * 57;
        float p[5];
        float gm = -1e30f;
        #pragma unroll
        for (int e = 0; e < 5; e++) gm = fmaxf(gm, L[e]);
        float gsum = 0.0f;
        #pragma unroll
        for (int e = 0; e < 5; e++) { p[e] = expf(L[e] - gm); gsum += p[e]; }
        const float ginv = 1.0f / gsum;
        #pragma unroll
        for (int e = 0; e < 5; e++) p[e] *= ginv;

        int idx[5] = {0, 1, 2, 3, 4};
        #pragma unroll
        for (int a = 0; a < 3; a++) {
            int best = a;
            #pragma unroll
            for (int q = a + 1; q < 5; q++)
                if (p[idx[q]] > p[idx[best]]) best = q;
            const int tmp = idx[a]; idx[a] = idx[best]; idx[best] = tmp;
        }

        float comb[10];
        #pragma unroll
        for (int c = 0; c < 10; c++) {
            float v = 0.0f;
            #pragma unroll
            for (int k = 0; k < 3; k++)
                v = fmaf(p[idx[k]], L[5 + idx[k] * 10 + c], v);
            comb[c] = v;
        }
        float cm = -1e30f;
        #pragma unroll
        for (int c = 0; c < 10; c++) cm = fmaxf(cm, comb[c]);
        float cs = 0.0f;
        float ex[10];
        #pragma unroll
        for (int c = 0; c < 10; c++) { ex[c] = expf(comb[c] - cm); cs += ex[c]; }
        const float inv = 1.0f / cs;
        float* o = out + (row0 + t) * 10;
        #pragma unroll
        for (int c = 0; c < 10; c++) o[c] = ex[c] * inv;
    }
}

// ==================== launcher ====================
extern "C" void kernel_launch(void* const* d_in, const int* in_sizes, int n_in,
                              void* d_out, int out_size) {
    const float* x  = (const float*)d_in[0];
    const float* w1 = (const float*)d_in[1];
    const float* b1 = (const float*)d_in[2];
    const float* w2 = (const float*)d_in[3];
    const float* b2 = (const float*)d_in[4];
    const float* gw = (const float*)d_in[5];
    const float* gb = (const float*)d_in[6];
    const float* ew = (const float*)d_in[7];
    const float* eb = (const float*)d_in[8];
    float* out = (float*)d_out;

    cudaFuncSetAttribute(conv_mma_kernel,
                         cudaFuncAttributeMaxDynamicSharedMemorySize, SM_TOTAL);

    pack_weights_kernel<<<(1600 * 56 + 255) / 256, 256>>>(gw, ew);
    prep_w2t_kernel<<<(64 * WTS + 255) / 256, 256>>>(w2);
    conv_mma_kernel<<<B, 256, SM_TOTAL>>>(x, w1, b1, b2);
    moe_head_kernel<<<B / 16, 256>>>(gb, eb, out);
}